// round 12
// baseline (speedup 1.0000x reference)
#include <cuda_runtime.h>
#include <cuda_fp16.h>
#include <cstdint>

#define H_IMG 200
#define W_IMG 200
#define VOLN  256
#define SUBS  16
#define NVOX  (VOLN*VOLN*VOLN)
#define CONV_BLOCKS 512
#define CONV_THREADS 256

// fp16 pair arrays: A[k]=(v[2k],v[2k+1]), B[k]=(v[2k+1],v[2k+2]) (global linear)
__device__ unsigned int g_volA[NVOX/2];
__device__ unsigned int g_volB[NVOX/2];

__device__ __forceinline__ unsigned int pack_h2(float a, float b) {
    __half2 h = __floats2half2_rn(a, b);
    return *reinterpret_cast<unsigned int*>(&h);
}

struct Geo {
    float ax, ay, az;
    float cx[4], cy[4], cz[4];
};

__device__ __forceinline__ Geo compute_geo(
    const float* k_inv, const float* rt_inv, float sdd, const float* aff)
{
    Geo g;
    float tx = rt_inv[3], ty = rt_inv[7], tz = rt_inv[11];
    float a00 = aff[0], a01 = aff[1], a02 = aff[2],  b0 = aff[3];
    float a10 = aff[4], a11 = aff[5], a12 = aff[6],  b1 = aff[7];
    float a20 = aff[8], a21 = aff[9], a22 = aff[10], b2 = aff[11];
    g.ax = a00*tx + a01*ty + a02*tz + b0;
    g.ay = a10*tx + a11*ty + a12*tz + b1;
    g.az = a20*tx + a21*ty + a22*tz + b2;
    const float us[4] = {0.f, (float)(W_IMG-1), 0.f, (float)(W_IMG-1)};
    const float vs[4] = {0.f, 0.f, (float)(H_IMG-1), (float)(H_IMG-1)};
    #pragma unroll
    for (int i = 0; i < 4; i++) {
        float uf = us[i], vf = vs[i];
        float tcx = (k_inv[0]*uf + k_inv[1]*vf + k_inv[2]) * sdd;
        float tcy = (k_inv[3]*uf + k_inv[4]*vf + k_inv[5]) * sdd;
        float tcz = (k_inv[6]*uf + k_inv[7]*vf + k_inv[8]) * sdd;
        float wx = rt_inv[0]*tcx + rt_inv[1]*tcy + rt_inv[2]*tcz + tx;
        float wy = rt_inv[4]*tcx + rt_inv[5]*tcy + rt_inv[6]*tcz + ty;
        float wz = rt_inv[8]*tcx + rt_inv[9]*tcy + rt_inv[10]*tcz + tz;
        g.cx[i] = a00*wx + a01*wy + a02*wz + b0;
        g.cy[i] = a10*wx + a11*wy + a12*wz + b1;
        g.cz[i] = a20*wx + a21*wy + a22*wz + b2;
    }
    return g;
}

// ---- prepass: grid-stride fp32 -> fp16 staggered pair arrays --------------
__global__ void __launch_bounds__(CONV_THREADS) convert_kernel(
    const float* __restrict__ vol,
    const float* __restrict__ k_inv,
    const float* __restrict__ rt_inv,
    const float* __restrict__ sdd_p,
    const float* __restrict__ aff)
{
    __shared__ float4 sb[32];

    if (threadIdx.x < 32) {
        int zc = threadIdx.x;
        int z0 = zc << 3;
        Geo g = compute_geo(k_inv, rt_inv, sdd_p[0], aff);

        float kzlo = (float)(z0 - 8), kzhi = (float)(z0 + 15);
        float xmin = 1e30f, xmax = -1e30f, ymin = 1e30f, ymax = -1e30f;
        #pragma unroll
        for (int i = 0; i < 4; i++) {
            float dz = g.cz[i] - g.az;
            float t0, t1;
            if (fabsf(dz) > 1e-6f) {
                float r = 1.0f / dz;
                t0 = fminf(fmaxf((kzlo - g.az) * r, 0.f), 1.f);
                t1 = fminf(fmaxf((kzhi - g.az) * r, 0.f), 1.f);
            } else { t0 = 0.f; t1 = 1.f; }
            float x0 = g.ax + t0 * (g.cx[i] - g.ax);
            float x1 = g.ax + t1 * (g.cx[i] - g.ax);
            float y0 = g.ay + t0 * (g.cy[i] - g.ay);
            float y1 = g.ay + t1 * (g.cy[i] - g.ay);
            xmin = fminf(xmin, fminf(x0, x1));  xmax = fmaxf(xmax, fmaxf(x0, x1));
            ymin = fminf(ymin, fminf(y0, y1));  ymax = fmaxf(ymax, fmaxf(y0, y1));
        }
        const float PAD = 8.0f;
        sb[zc] = make_float4(xmin - PAD, xmax + PAD, ymin - PAD, ymax + PAD);
    }
    __syncthreads();

    const int NITEMS = NVOX / 8;   // 2,097,152
    const int stride = CONV_BLOCKS * CONV_THREADS;

    for (int item = blockIdx.x * blockDim.x + threadIdx.x;
         item < NITEMS; item += stride) {
        int zc = item & 31;
        int iy = (item >> 5) & 255;
        int ix = item >> 13;

        float4 b = sb[zc];
        if ((float)ix < b.x || (float)ix > b.y ||
            (float)iy < b.z || (float)iy > b.w) continue;

        int z0 = zc << 3;
        int gbase = (ix << 16) + (iy << 8) + z0;
        float4 L0 = *(const float4*)(vol + gbase);
        float4 L1 = *(const float4*)(vol + gbase + 4);
        float  ve = vol[(gbase + 8 <= NVOX - 1) ? (gbase + 8) : (NVOX - 1)];

        uint4 wa, wb;
        wa.x = pack_h2(L0.x, L0.y);
        wa.y = pack_h2(L0.z, L0.w);
        wa.z = pack_h2(L1.x, L1.y);
        wa.w = pack_h2(L1.z, L1.w);
        wb.x = pack_h2(L0.y, L0.z);
        wb.y = pack_h2(L0.w, L1.x);
        wb.z = pack_h2(L1.y, L1.z);
        wb.w = pack_h2(L1.w, ve);

        ((uint4*)g_volA)[gbase >> 3] = wa;
        ((uint4*)g_volB)[gbase >> 3] = wb;
    }
}

// ---- unguarded fp16 interior sample --------------------------------------
__device__ __forceinline__ float sample_fast(float x, float y, float z)
{
    float fx = floorf(x), fy = floorf(y), fz = floorf(z);
    int ix = (int)fx, iy = (int)fy, iz = (int)fz;
    float wx = x - fx, wy = y - fy, wz = z - fz;

    int wbase = ((ix << 16) + (iy << 8) + iz) >> 1;
    const unsigned int* arr = (iz & 1) ? g_volB : g_volA;
    unsigned int w00 = arr[wbase];
    unsigned int w01 = arr[wbase + 128];
    unsigned int w10 = arr[wbase + 32768];
    unsigned int w11 = arr[wbase + 32768 + 128];
    float2 f00 = __half22float2(*reinterpret_cast<__half2*>(&w00));
    float2 f01 = __half22float2(*reinterpret_cast<__half2*>(&w01));
    float2 f10 = __half22float2(*reinterpret_cast<__half2*>(&w10));
    float2 f11 = __half22float2(*reinterpret_cast<__half2*>(&w11));
    float c00 = f00.x + wz * (f00.y - f00.x);
    float c01 = f01.x + wz * (f01.y - f01.x);
    float c10 = f10.x + wz * (f10.y - f10.x);
    float c11 = f11.x + wz * (f11.y - f11.x);
    float c0  = c00 + wy * (c01 - c00);
    float c1  = c10 + wy * (c11 - c10);
    return c0 + wx * (c1 - c0);
}

// ---- guarded sample (fp16 interior / exact fp32 boundary) ----------------
__device__ __forceinline__ float sample_guard(float x, float y, float z,
                                              const float* __restrict__ vol)
{
    float fx = floorf(x), fy = floorf(y), fz = floorf(z);
    int ix = (int)fx, iy = (int)fy, iz = (int)fz;
    float wx = x - fx, wy = y - fy, wz = z - fz;

    if (ix >= 0 && ix < VOLN - 1 &&
        iy >= 0 && iy < VOLN - 1 &&
        iz >= 0 && iz < VOLN - 1) {
        return sample_fast(x, y, z);
    }
    bool x0 = ((unsigned)ix      < (unsigned)VOLN);
    bool x1 = ((unsigned)(ix+1)  < (unsigned)VOLN);
    bool y0 = ((unsigned)iy      < (unsigned)VOLN);
    bool y1 = ((unsigned)(iy+1)  < (unsigned)VOLN);
    bool z0 = ((unsigned)iz      < (unsigned)VOLN);
    bool z1 = ((unsigned)(iz+1)  < (unsigned)VOLN);
    if (!((x0|x1) && (y0|y1) && (z0|z1))) return 0.0f;
    long base = (long)ix * 65536 + (long)iy * 256 + (long)iz;
    float v000 = (x0 && y0 && z0) ? vol[base]               : 0.0f;
    float v001 = (x0 && y0 && z1) ? vol[base + 1]           : 0.0f;
    float v010 = (x0 && y1 && z0) ? vol[base + 256]         : 0.0f;
    float v011 = (x0 && y1 && z1) ? vol[base + 257]         : 0.0f;
    float v100 = (x1 && y0 && z0) ? vol[base + 65536]       : 0.0f;
    float v101 = (x1 && y0 && z1) ? vol[base + 65537]       : 0.0f;
    float v110 = (x1 && y1 && z0) ? vol[base + 65536 + 256] : 0.0f;
    float v111 = (x1 && y1 && z1) ? vol[base + 65536 + 257] : 0.0f;
    float c00 = v000 + wz * (v001 - v000);
    float c01 = v010 + wz * (v011 - v010);
    float c10 = v100 + wz * (v101 - v100);
    float c11 = v110 + wz * (v111 - v110);
    float c0  = c00 + wy * (c01 - c00);
    float c1  = c10 + wy * (c11 - c10);
    return c0 + wx * (c1 - c0);
}

// slab clip of c + t*d against [lo,hi]^3, over t in [tmin0,tmax0]
__device__ __forceinline__ void clip3(
    const float* c, const float* d, float lo, float hi,
    float& tmin, float& tmax)
{
    #pragma unroll
    for (int a = 0; a < 3; a++) {
        if (fabsf(d[a]) > 1e-8f) {
            float r  = 1.0f / d[a];
            float t0 = (lo - c[a]) * r;
            float t1 = (hi - c[a]) * r;
            float l = fminf(t0, t1), h = fmaxf(t0, t1);
            tmin = fmaxf(tmin, l);
            tmax = fminf(tmax, h);
        } else if (c[a] < lo || c[a] > hi) {
            tmin = 1.0f; tmax = 0.0f;
        }
    }
}

// ---------------- main kernel ----------------
__global__ void __launch_bounds__(256) drr_kernel(
    const float* __restrict__ vol,
    const float* __restrict__ k_inv,
    const float* __restrict__ rt_inv,
    const float* __restrict__ sdd_p,
    const float* __restrict__ aff,
    const int*   __restrict__ ns_p,
    float* __restrict__ out)
{
    int gtid = blockIdx.x * blockDim.x + threadIdx.x;
    int pix  = gtid >> 4;
    int sub  = gtid & (SUBS - 1);
    if (pix >= H_IMG * W_IMG) return;

    int u = pix % W_IMG;
    int v = pix / W_IMG;

    float sdd = sdd_p[0];
    int   ns  = ns_p[0];
    float nm1 = (float)(ns - 1);
    float inv_nm1 = 1.0f / nm1;

    float uf = (float)u, vf = (float)v;

    float tcx = (k_inv[0]*uf + k_inv[1]*vf + k_inv[2]) * sdd;
    float tcy = (k_inv[3]*uf + k_inv[4]*vf + k_inv[5]) * sdd;
    float tcz = (k_inv[6]*uf + k_inv[7]*vf + k_inv[8]) * sdd;

    float tx = rt_inv[3], ty = rt_inv[7], tz = rt_inv[11];
    float tgx = rt_inv[0]*tcx + rt_inv[1]*tcy + rt_inv[2]*tcz + tx;
    float tgy = rt_inv[4]*tcx + rt_inv[5]*tcy + rt_inv[6]*tcz + ty;
    float tgz = rt_inv[8]*tcx + rt_inv[9]*tcy + rt_inv[10]*tcz + tz;

    float rx = tgx - tx, ry = tgy - ty, rz = tgz - tz;
    float step = sqrtf(rx*rx + ry*ry + rz*rz) * inv_nm1;

    float a00 = aff[0], a01 = aff[1], a02 = aff[2],  b0 = aff[3];
    float a10 = aff[4], a11 = aff[5], a12 = aff[6],  b1 = aff[7];
    float a20 = aff[8], a21 = aff[9], a22 = aff[10], b2 = aff[11];

    float c3[3], d3[3];
    c3[0] = a00*tx + a01*ty + a02*tz + b0;
    c3[1] = a10*tx + a11*ty + a12*tz + b1;
    c3[2] = a20*tx + a21*ty + a22*tz + b2;
    d3[0] = a00*rx + a01*ry + a02*rz;
    d3[1] = a10*rx + a11*ry + a12*rz;
    d3[2] = a20*rx + a21*ry + a22*rz;
    float cx = c3[0], cy = c3[1], cz = c3[2];
    float dx = d3[0], dy = d3[1], dz = d3[2];

    // outer clip (contribution possible) and inner clip (provably interior)
    float tmin = 0.0f, tmax = 1.0f;
    clip3(c3, d3, -1.0f - 1e-3f, (float)VOLN + 1e-3f, tmin, tmax);
    float tminI = 0.0f, tmaxI = 1.0f;
    clip3(c3, d3, 0.01f, (float)VOLN - 1.0f - 0.01f, tminI, tmaxI);

    int s0 = 0, s1 = -1;
    if (tmax >= tmin) {
        s0 = (int)floorf(tmin * nm1);  if (s0 < 0) s0 = 0;
        s1 = (int)ceilf (tmax * nm1);  if (s1 > ns - 1) s1 = ns - 1;
    }
    int sIa = ns, sIb = -1;
    if (tmaxI >= tminI) {
        sIa = (int)ceilf (tminI * nm1);  if (sIa < s0) sIa = s0;
        sIb = (int)floorf(tmaxI * nm1);  if (sIb > s1) sIb = s1;
    }

    float sum0 = 0.0f, sum1 = 0.0f;
    int s = s0 + sub;

    // guarded head (shell crossing; exact fp32 boundary handling)
    for (; s <= s1 && s < sIa; s += SUBS) {
        float t = (float)s * inv_nm1;
        sum0 += sample_guard(fmaf(t, dx, cx), fmaf(t, dy, cy), fmaf(t, dz, cz), vol);
    }
    // unguarded interior, ILP2
    for (; s + SUBS <= sIb; s += 2 * SUBS) {
        float ta = (float)s * inv_nm1;
        float tb = (float)(s + SUBS) * inv_nm1;
        sum0 += sample_fast(fmaf(ta, dx, cx), fmaf(ta, dy, cy), fmaf(ta, dz, cz));
        sum1 += sample_fast(fmaf(tb, dx, cx), fmaf(tb, dy, cy), fmaf(tb, dz, cz));
    }
    if (s <= sIb) {
        float t = (float)s * inv_nm1;
        sum0 += sample_fast(fmaf(t, dx, cx), fmaf(t, dy, cy), fmaf(t, dz, cz));
        s += SUBS;
    }
    // guarded tail
    for (; s <= s1; s += SUBS) {
        float t = (float)s * inv_nm1;
        sum1 += sample_guard(fmaf(t, dx, cx), fmaf(t, dy, cy), fmaf(t, dz, cz), vol);
    }

    float sum = sum0 + sum1;

    sum += __shfl_xor_sync(0xFFFFFFFFu, sum, 8, SUBS);
    sum += __shfl_xor_sync(0xFFFFFFFFu, sum, 4, SUBS);
    sum += __shfl_xor_sync(0xFFFFFFFFu, sum, 2, SUBS);
    sum += __shfl_xor_sync(0xFFFFFFFFu, sum, 1, SUBS);

    if (sub == 0) out[pix] = sum * step;
}

extern "C" void kernel_launch(void* const* d_in, const int* in_sizes, int n_in,
                              void* d_out, int out_size)
{
    const float* vol    = (const float*)d_in[0];
    const float* k_inv  = (const float*)d_in[1];
    const float* rt_inv = (const float*)d_in[2];
    const float* sdd    = (const float*)d_in[3];
    const float* aff    = (const float*)d_in[4];
    const int*   ns     = (const int*)  d_in[5];
    float* out = (float*)d_out;

    convert_kernel<<<CONV_BLOCKS, CONV_THREADS>>>(vol, k_inv, rt_inv, sdd, aff);

    int total = H_IMG * W_IMG * SUBS;
    int block = 256;
    int grid  = (total + block - 1) / block;
    drr_kernel<<<grid, block>>>(vol, k_inv, rt_inv, sdd, aff, ns, out);
}

// round 13
// speedup vs baseline: 1.1393x; 1.1393x over previous
#include <cuda_runtime.h>
#include <cuda_fp16.h>
#include <cstdint>

#define H_IMG 200
#define W_IMG 200
#define VOLN  256
#define SUBS  16
#define NVOX  (VOLN*VOLN*VOLN)
#define CONV_BLOCKS 512
#define CONV_THREADS 256

// fp16 pair arrays: A[k]=(v[2k],v[2k+1]), B[k]=(v[2k+1],v[2k+2]) (global linear)
__device__ __half2 g_volA[NVOX/2];
__device__ __half2 g_volB[NVOX/2];

__device__ __forceinline__ unsigned int pack_h2(float a, float b) {
    __half2 h = __floats2half2_rn(a, b);
    return *reinterpret_cast<unsigned int*>(&h);
}

struct Geo {
    float ax, ay, az;
    float cx[4], cy[4], cz[4];
};

__device__ __forceinline__ Geo compute_geo(
    const float* k_inv, const float* rt_inv, float sdd, const float* aff)
{
    Geo g;
    float tx = rt_inv[3], ty = rt_inv[7], tz = rt_inv[11];
    float a00 = aff[0], a01 = aff[1], a02 = aff[2],  b0 = aff[3];
    float a10 = aff[4], a11 = aff[5], a12 = aff[6],  b1 = aff[7];
    float a20 = aff[8], a21 = aff[9], a22 = aff[10], b2 = aff[11];
    g.ax = a00*tx + a01*ty + a02*tz + b0;
    g.ay = a10*tx + a11*ty + a12*tz + b1;
    g.az = a20*tx + a21*ty + a22*tz + b2;
    const float us[4] = {0.f, (float)(W_IMG-1), 0.f, (float)(W_IMG-1)};
    const float vs[4] = {0.f, 0.f, (float)(H_IMG-1), (float)(H_IMG-1)};
    #pragma unroll
    for (int i = 0; i < 4; i++) {
        float uf = us[i], vf = vs[i];
        float tcx = (k_inv[0]*uf + k_inv[1]*vf + k_inv[2]) * sdd;
        float tcy = (k_inv[3]*uf + k_inv[4]*vf + k_inv[5]) * sdd;
        float tcz = (k_inv[6]*uf + k_inv[7]*vf + k_inv[8]) * sdd;
        float wx = rt_inv[0]*tcx + rt_inv[1]*tcy + rt_inv[2]*tcz + tx;
        float wy = rt_inv[4]*tcx + rt_inv[5]*tcy + rt_inv[6]*tcz + ty;
        float wz = rt_inv[8]*tcx + rt_inv[9]*tcy + rt_inv[10]*tcz + tz;
        g.cx[i] = a00*wx + a01*wy + a02*wz + b0;
        g.cy[i] = a10*wx + a11*wy + a12*wz + b1;
        g.cz[i] = a20*wx + a21*wy + a22*wz + b2;
    }
    return g;
}

// ---- prepass: grid-stride fp32 -> fp16 staggered pair arrays --------------
__global__ void __launch_bounds__(CONV_THREADS) convert_kernel(
    const float* __restrict__ vol,
    const float* __restrict__ k_inv,
    const float* __restrict__ rt_inv,
    const float* __restrict__ sdd_p,
    const float* __restrict__ aff)
{
    __shared__ float4 sb[32];

    if (threadIdx.x < 32) {
        int zc = threadIdx.x;
        int z0 = zc << 3;
        Geo g = compute_geo(k_inv, rt_inv, sdd_p[0], aff);

        // samples landing in this chunk read iz..iz+1 with iz in [z0, z0+7];
        // z-window [z0-1, z0+9] is conservative, PAD=3 covers fp drift.
        float kzlo = (float)(z0 - 1), kzhi = (float)(z0 + 9);
        float xmin = 1e30f, xmax = -1e30f, ymin = 1e30f, ymax = -1e30f;
        #pragma unroll
        for (int i = 0; i < 4; i++) {
            float dz = g.cz[i] - g.az;
            float t0, t1;
            if (fabsf(dz) > 1e-6f) {
                float r = 1.0f / dz;
                t0 = fminf(fmaxf((kzlo - g.az) * r, 0.f), 1.f);
                t1 = fminf(fmaxf((kzhi - g.az) * r, 0.f), 1.f);
            } else { t0 = 0.f; t1 = 1.f; }
            float x0 = g.ax + t0 * (g.cx[i] - g.ax);
            float x1 = g.ax + t1 * (g.cx[i] - g.ax);
            float y0 = g.ay + t0 * (g.cy[i] - g.ay);
            float y1 = g.ay + t1 * (g.cy[i] - g.ay);
            xmin = fminf(xmin, fminf(x0, x1));  xmax = fmaxf(xmax, fmaxf(x0, x1));
            ymin = fminf(ymin, fminf(y0, y1));  ymax = fmaxf(ymax, fmaxf(y0, y1));
        }
        const float PAD = 3.0f;
        sb[zc] = make_float4(xmin - PAD, xmax + PAD, ymin - PAD, ymax + PAD);
    }
    __syncthreads();

    const int NITEMS = NVOX / 8;   // 2,097,152
    const int stride = CONV_BLOCKS * CONV_THREADS;

    for (int item = blockIdx.x * blockDim.x + threadIdx.x;
         item < NITEMS; item += stride) {
        int zc = item & 31;
        int iy = (item >> 5) & 255;
        int ix = item >> 13;

        float4 b = sb[zc];
        if ((float)ix < b.x || (float)ix > b.y ||
            (float)iy < b.z || (float)iy > b.w) continue;

        int z0 = zc << 3;
        int gbase = (ix << 16) + (iy << 8) + z0;
        float4 L0 = *(const float4*)(vol + gbase);
        float4 L1 = *(const float4*)(vol + gbase + 4);
        float  ve = vol[(gbase + 8 <= NVOX - 1) ? (gbase + 8) : (NVOX - 1)];

        uint4 wa, wb;
        wa.x = pack_h2(L0.x, L0.y);
        wa.y = pack_h2(L0.z, L0.w);
        wa.z = pack_h2(L1.x, L1.y);
        wa.w = pack_h2(L1.z, L1.w);
        wb.x = pack_h2(L0.y, L0.z);
        wb.y = pack_h2(L0.w, L1.x);
        wb.z = pack_h2(L1.y, L1.z);
        wb.w = pack_h2(L1.w, ve);

        ((uint4*)g_volA)[gbase >> 3] = wa;
        ((uint4*)g_volB)[gbase >> 3] = wb;
    }
}

// ---- fp16 sample with half2-SIMD lerp (guarded; fp32 boundary path) ------
__device__ __forceinline__ float sample_h2(float x, float y, float z,
                                           const float* __restrict__ vol)
{
    float fx = floorf(x), fy = floorf(y), fz = floorf(z);
    int ix = (int)fx, iy = (int)fy, iz = (int)fz;
    float wx = x - fx, wy = y - fy, wz = z - fz;

    if (ix >= 0 && ix < VOLN - 1 &&
        iy >= 0 && iy < VOLN - 1 &&
        iz >= 0 && iz < VOLN - 1) {
        int wbase = ((ix << 16) + (iy << 8) + iz) >> 1;
        const __half2* arr = (iz & 1) ? g_volB : g_volA;
        __half2 p00 = arr[wbase];                  // (v000, v001)
        __half2 p01 = arr[wbase + 128];            // (v010, v011)
        __half2 p10 = arr[wbase + 32768];          // (v100, v101)
        __half2 p11 = arr[wbase + 32768 + 128];    // (v110, v111)

        __half2 wz2 = __float2half2_rn(wz);
        __half2 wy2 = __float2half2_rn(wy);

        // z-lerp two corners at a time
        __half2 lo0 = __lows2half2 (p00, p01);     // (v000, v010)
        __half2 hi0 = __highs2half2(p00, p01);     // (v001, v011)
        __half2 cz0 = __hfma2(wz2, __hsub2(hi0, lo0), lo0);   // (c00, c01)
        __half2 lo1 = __lows2half2 (p10, p11);
        __half2 hi1 = __highs2half2(p10, p11);
        __half2 cz1 = __hfma2(wz2, __hsub2(hi1, lo1), lo1);   // (c10, c11)

        // y-lerp: (c0, c1) in one half2
        __half2 loy = __lows2half2 (cz0, cz1);     // (c00, c10)
        __half2 hiy = __highs2half2(cz0, cz1);     // (c01, c11)
        __half2 cy2 = __hfma2(wy2, __hsub2(hiy, loy), loy);   // (c0, c1)

        float2 f = __half22float2(cy2);
        return f.x + wx * (f.y - f.x);
    }
    bool x0 = ((unsigned)ix      < (unsigned)VOLN);
    bool x1 = ((unsigned)(ix+1)  < (unsigned)VOLN);
    bool y0 = ((unsigned)iy      < (unsigned)VOLN);
    bool y1 = ((unsigned)(iy+1)  < (unsigned)VOLN);
    bool z0 = ((unsigned)iz      < (unsigned)VOLN);
    bool z1 = ((unsigned)(iz+1)  < (unsigned)VOLN);
    if (!((x0|x1) && (y0|y1) && (z0|z1))) return 0.0f;
    long base = (long)ix * 65536 + (long)iy * 256 + (long)iz;
    float v000 = (x0 && y0 && z0) ? vol[base]               : 0.0f;
    float v001 = (x0 && y0 && z1) ? vol[base + 1]           : 0.0f;
    float v010 = (x0 && y1 && z0) ? vol[base + 256]         : 0.0f;
    float v011 = (x0 && y1 && z1) ? vol[base + 257]         : 0.0f;
    float v100 = (x1 && y0 && z0) ? vol[base + 65536]       : 0.0f;
    float v101 = (x1 && y0 && z1) ? vol[base + 65537]       : 0.0f;
    float v110 = (x1 && y1 && z0) ? vol[base + 65536 + 256] : 0.0f;
    float v111 = (x1 && y1 && z1) ? vol[base + 65536 + 257] : 0.0f;
    float c00 = v000 + wz * (v001 - v000);
    float c01 = v010 + wz * (v011 - v010);
    float c10 = v100 + wz * (v101 - v100);
    float c11 = v110 + wz * (v111 - v110);
    float c0  = c00 + wy * (c01 - c00);
    float c1  = c10 + wy * (c11 - c10);
    return c0 + wx * (c1 - c0);
}

// ---------------- main kernel ----------------
__global__ void __launch_bounds__(256) drr_kernel(
    const float* __restrict__ vol,
    const float* __restrict__ k_inv,
    const float* __restrict__ rt_inv,
    const float* __restrict__ sdd_p,
    const float* __restrict__ aff,
    const int*   __restrict__ ns_p,
    float* __restrict__ out)
{
    int gtid = blockIdx.x * blockDim.x + threadIdx.x;
    int pix  = gtid >> 4;
    int sub  = gtid & (SUBS - 1);
    if (pix >= H_IMG * W_IMG) return;

    int u = pix % W_IMG;
    int v = pix / W_IMG;

    float sdd = sdd_p[0];
    int   ns  = ns_p[0];
    float nm1 = (float)(ns - 1);
    float inv_nm1 = 1.0f / nm1;

    float uf = (float)u, vf = (float)v;

    float tcx = (k_inv[0]*uf + k_inv[1]*vf + k_inv[2]) * sdd;
    float tcy = (k_inv[3]*uf + k_inv[4]*vf + k_inv[5]) * sdd;
    float tcz = (k_inv[6]*uf + k_inv[7]*vf + k_inv[8]) * sdd;

    float tx = rt_inv[3], ty = rt_inv[7], tz = rt_inv[11];
    float tgx = rt_inv[0]*tcx + rt_inv[1]*tcy + rt_inv[2]*tcz + tx;
    float tgy = rt_inv[4]*tcx + rt_inv[5]*tcy + rt_inv[6]*tcz + ty;
    float tgz = rt_inv[8]*tcx + rt_inv[9]*tcy + rt_inv[10]*tcz + tz;

    float rx = tgx - tx, ry = tgy - ty, rz = tgz - tz;
    float step = sqrtf(rx*rx + ry*ry + rz*rz) * inv_nm1;

    float a00 = aff[0], a01 = aff[1], a02 = aff[2],  b0 = aff[3];
    float a10 = aff[4], a11 = aff[5], a12 = aff[6],  b1 = aff[7];
    float a20 = aff[8], a21 = aff[9], a22 = aff[10], b2 = aff[11];

    float cx = a00*tx + a01*ty + a02*tz + b0;
    float cy = a10*tx + a11*ty + a12*tz + b1;
    float cz = a20*tx + a21*ty + a22*tz + b2;
    float dx = a00*rx + a01*ry + a02*rz;
    float dy = a10*rx + a11*ry + a12*rz;
    float dz = a20*rx + a21*ry + a22*rz;

    const float LO = -1.0f - 1e-3f;
    const float HI = (float)VOLN + 1e-3f;
    float tmin = 0.0f, tmax = 1.0f;
    {
        float c[3] = {cx, cy, cz};
        float d[3] = {dx, dy, dz};
        #pragma unroll
        for (int a = 0; a < 3; a++) {
            if (fabsf(d[a]) > 1e-8f) {
                float r  = 1.0f / d[a];
                float t0 = (LO - c[a]) * r;
                float t1 = (HI - c[a]) * r;
                float lo = fminf(t0, t1), hi = fmaxf(t0, t1);
                tmin = fmaxf(tmin, lo);
                tmax = fminf(tmax, hi);
            } else if (c[a] < LO || c[a] > HI) {
                tmin = 1.0f; tmax = 0.0f;
            }
        }
    }

    int s0 = 0, s1 = -1;
    if (tmax >= tmin) {
        s0 = (int)floorf(tmin * nm1);  if (s0 < 0) s0 = 0;
        s1 = (int)ceilf (tmax * nm1);  if (s1 > ns - 1) s1 = ns - 1;
    }

    float sum0 = 0.0f, sum1 = 0.0f;

    // 2 independent samples per lane per trip (s, s+16)
    int s = s0 + sub;
    for (; s + SUBS <= s1; s += 2 * SUBS) {
        float ta = (float)s * inv_nm1;
        float tb = (float)(s + SUBS) * inv_nm1;
        float xa = fmaf(ta, dx, cx), ya = fmaf(ta, dy, cy), za = fmaf(ta, dz, cz);
        float xb = fmaf(tb, dx, cx), yb = fmaf(tb, dy, cy), zb = fmaf(tb, dz, cz);
        sum0 += sample_h2(xa, ya, za, vol);
        sum1 += sample_h2(xb, yb, zb, vol);
    }
    if (s <= s1) {
        float ta = (float)s * inv_nm1;
        float xa = fmaf(ta, dx, cx), ya = fmaf(ta, dy, cy), za = fmaf(ta, dz, cz);
        sum0 += sample_h2(xa, ya, za, vol);
    }

    float sum = sum0 + sum1;

    sum += __shfl_xor_sync(0xFFFFFFFFu, sum, 8, SUBS);
    sum += __shfl_xor_sync(0xFFFFFFFFu, sum, 4, SUBS);
    sum += __shfl_xor_sync(0xFFFFFFFFu, sum, 2, SUBS);
    sum += __shfl_xor_sync(0xFFFFFFFFu, sum, 1, SUBS);

    if (sub == 0) out[pix] = sum * step;
}

extern "C" void kernel_launch(void* const* d_in, const int* in_sizes, int n_in,
                              void* d_out, int out_size)
{
    const float* vol    = (const float*)d_in[0];
    const float* k_inv  = (const float*)d_in[1];
    const float* rt_inv = (const float*)d_in[2];
    const float* sdd    = (const float*)d_in[3];
    const float* aff    = (const float*)d_in[4];
    const int*   ns     = (const int*)  d_in[5];
    float* out = (float*)d_out;

    convert_kernel<<<CONV_BLOCKS, CONV_THREADS>>>(vol, k_inv, rt_inv, sdd, aff);

    int total = H_IMG * W_IMG * SUBS;
    int block = 256;
    int grid  = (total + block - 1) / block;
    drr_kernel<<<grid, block>>>(vol, k_inv, rt_inv, sdd, aff, ns, out);
}